// round 12
// baseline (speedup 1.0000x reference)
#include <cuda_runtime.h>

#define SEQ   1024
#define BATCH 512
#define NC    48
#define FULL  0xffffffffu

__device__ int g_perm[BATCH];   // rank r -> batch index (descending length)

// ---- packed f32x2 helpers (sm_103a) ------------------------------------
static __device__ __forceinline__ unsigned long long pk2(float lo, float hi) {
    unsigned long long r;
    asm("mov.b64 %0, {%1,%2};" : "=l"(r) : "f"(lo), "f"(hi));
    return r;
}
static __device__ __forceinline__ unsigned long long fma2(
    unsigned long long a, unsigned long long b, unsigned long long c) {
    unsigned long long d;
    asm("fma.rn.f32x2 %0, %1, %2, %3;" : "=l"(d) : "l"(a), "l"(b), "l"(c));
    return d;
}
static __device__ __forceinline__ unsigned long long add2(
    unsigned long long a, unsigned long long b) {
    unsigned long long d;
    asm("add.rn.f32x2 %0, %1, %2;" : "=l"(d) : "l"(a), "l"(b));
    return d;
}
static __device__ __forceinline__ float hadd2(unsigned long long v) {
    float lo, hi;
    asm("mov.b64 {%0,%1}, %2;" : "=f"(lo), "=f"(hi) : "l"(v));
    return lo + hi;
}
static __device__ __forceinline__ float lo2(unsigned long long v) {
    float lo, hi;
    asm("mov.b64 {%0,%1}, %2;" : "=f"(lo), "=f"(hi) : "l"(v));
    return lo;
}
static __device__ __forceinline__ void lds16(
    unsigned long long& x, unsigned long long& y, unsigned int addr) {
    asm volatile("ld.shared.v2.u64 {%0,%1}, [%2];" : "=l"(x), "=l"(y) : "r"(addr));
}
static __device__ __forceinline__ float frcp(float x) {
    float r; asm("rcp.approx.f32 %0, %1;" : "=f"(r) : "f"(x)); return r;
}

// ---------------------------------------------------------------------------
// Rank prologue: counting rank by (length desc, index asc). Deterministic.
// ---------------------------------------------------------------------------
__global__ __launch_bounds__(BATCH) void crf_rank_kernel(
    const int* __restrict__ lengths)
{
    __shared__ int sl[BATCH];
    const int i = threadIdx.x;
    sl[i] = lengths[i];
    __syncthreads();
    const int Li = sl[i];
    int r = 0;
    for (int j = 0; j < BATCH; ++j) {
        const int Lj = sl[j];
        r += (Lj > Li) || (Lj == Li && j < i);
    }
    g_perm[r] = i;
}

// 48-fma2 dot (R5 version — lowest LATENCY measured; no shfl join in the
// chain). Lane owns class A = lane (24 row-pairs, TA) and class
// B = lane+32 (24 row-pairs, TB; TB == 0 for lanes >= 16 so dotB is 0
// there — wasted fma THROUGHPUT, free in the 4-warp latency-bound regime).
// 12 LDS.128 + 8 independent 6-deep fma2 chains.
// rfirst = exchanged[0] (delayed-renorm reference).
#define CRF_DOT48(sb, TA, TB, dotA, dotB, rfirst)                             \
    {                                                                         \
        unsigned long long cA0=0ull,cA1=0ull,cA2=0ull,cA3=0ull;               \
        unsigned long long cB0=0ull,cB1=0ull,cB2=0ull,cB3=0ull;               \
        unsigned long long e_first=0ull;                                      \
        _Pragma("unroll")                                                     \
        for (int k = 0; k < 12; k += 2) {                                     \
            unsigned long long x01, x23, y01, y23;                            \
            lds16(x01, x23, (sb) + 16u * k);                                  \
            lds16(y01, y23, (sb) + 16u * (k + 1));                            \
            if (k == 0) e_first = x01;                                        \
            cA0 = fma2(x01, TA[2 * k],     cA0);                              \
            cA1 = fma2(x23, TA[2 * k + 1], cA1);                              \
            cB0 = fma2(x01, TB[2 * k],     cB0);                              \
            cB1 = fma2(x23, TB[2 * k + 1], cB1);                              \
            cA2 = fma2(y01, TA[2 * k + 2], cA2);                              \
            cA3 = fma2(y23, TA[2 * k + 3], cA3);                              \
            cB2 = fma2(y01, TB[2 * k + 2], cB2);                              \
            cB3 = fma2(y23, TB[2 * k + 3], cB3);                              \
        }                                                                     \
        rfirst = lo2(e_first);                                                \
        dotA = hadd2(add2(add2(cA0, cA1), add2(cA2, cA3)));                   \
        dotB = hadd2(add2(add2(cB0, cB1), add2(cB2, cB3)));                   \
    }

// ---------------------------------------------------------------------------
// Meet-in-the-middle CRF, contention-optimal partition:
// block k owns length-ranks {2k, 2k+1, 511-2k, 510-2k} (slots 0..3):
// two LONG + two TINY chains per block; each SMSP gets one long chain warp
// plus one tiny partner that retires almost immediately -> the long chains
// run at the single-warp latency floor.
// Warp->(slot, role):  w0:(0,F) w1:(0,B) w2:(1,F) w3:(1,B)
//                      w4:(3,B) w5:(3,F) w6:(2,B) w7:(2,F)
// ---------------------------------------------------------------------------
__global__ __launch_bounds__(256, 1) void crf_mitm_kernel(
    const float* __restrict__ scores,
    const int*   __restrict__ target,
    const int*   __restrict__ lengths,
    const float* __restrict__ trans,
    float*       __restrict__ out)
{
    __shared__ float sh_ex[8][2][64];  // per-warp ping-pong exchange buffers
    __shared__ float sh_v[4][64];      // backward result vectors (48 + pad)
    __shared__ float sh_mb[4];         // backward Mlog
    __shared__ float sh_xb[4];         // backward X partial

    const int wid  = threadIdx.x >> 5;
    const int lane = threadIdx.x & 31;

    const int  slot  = (wid < 4) ? (wid >> 1) : (3 - ((wid - 4) >> 1));
    const bool isfwd = !((wid & 1) ^ ((wid >> 2) & 1));

    const int k    = blockIdx.x;
    const int rank = (slot == 0) ? (2 * k)
                   : (slot == 1) ? (2 * k + 1)
                   : (slot == 2) ? (511 - 2 * k)
                   :               (510 - 2 * k);
    const int b    = g_perm[rank];

    const int L = lengths[b];
    const int h = (L >= 2) ? (L >> 1) : 1;

    const int  cA = lane;                      // owned class A (0..31)
    const bool v1 = (lane < 16);
    const int  cB = v1 ? (lane + 32) : lane;   // owned class B (dup-safe)

    const float* spA = scores + (size_t)b * NC + cA;
    const float* spB = scores + (size_t)b * NC + cB;
    const size_t rs  = (size_t)BATCH * NC;

    unsigned int shbase[2];
    shbase[0] = (unsigned int)__cvta_generic_to_shared(&sh_ex[wid][0][0]);
    shbase[1] = (unsigned int)__cvta_generic_to_shared(&sh_ex[wid][1][0]);

    float aA = 0.f, aB = 0.f, Mf = 0.f, Xpart = 0.f;

    if (isfwd) {
        // ===================== FORWARD role =================================
        for (int t = lane; t < h; t += 32) {
            const int tgt = target[t * BATCH + b];
            float v = scores[((size_t)t * BATCH + b) * NC + tgt];
            if (t > 0) v += trans[target[(t - 1) * BATCH + b] * NC + tgt];
            Xpart += v;
        }
#pragma unroll
        for (int o = 16; o > 0; o >>= 1)
            Xpart += __shfl_xor_sync(FULL, Xpart, o);

        // exp(E^T): TA/TB[j] = (E[2j][c], E[2j+1][c]) for c = cA / cB.
        unsigned long long TA[24], TB[24];
#pragma unroll
        for (int j = 0; j < 24; ++j) {
            TA[j] = pk2(__expf(trans[(2*j)*NC + cA]), __expf(trans[(2*j+1)*NC + cA]));
            TB[j] = v1 ? pk2(__expf(trans[(2*j)*NC + cB]), __expf(trans[(2*j+1)*NC + cB]))
                       : 0ull;
        }

        aA = __expf(spA[0]);
        aB = v1 ? __expf(spB[0]) : 0.0f;

        float pA[4], pB[4];
#pragma unroll
        for (int kk = 0; kk < 4; ++kk) {
            pA[kk] = spA[(size_t)(1 + kk) * rs];
            pB[kk] = spB[(size_t)(1 + kk) * rs];
        }

#define FWD_STEP(T, SLOT)                                                     \
    {                                                                         \
        const float sA = pA[SLOT];                                            \
        const float sB = pB[SLOT];                                            \
        pA[SLOT] = spA[(size_t)((T) + 4) * rs];                               \
        pB[SLOT] = spB[(size_t)((T) + 4) * rs];                               \
        const float wA = __expf(sA);                                          \
        const float wB = __expf(sB);                                          \
        {                                                                     \
            float* shp = &sh_ex[wid][(SLOT) & 1][0];                          \
            shp[lane]      = aA;                                              \
            shp[32 + lane] = aB;                                              \
        }                                                                     \
        __syncwarp();                                                         \
        float dotA, dotB, r;                                                  \
        CRF_DOT48(shbase[(SLOT) & 1], TA, TB, dotA, dotB, r)                  \
        const float inv = frcp(r);                                            \
        Mf += __logf(r);                                                      \
        aA = dotA * (wA * inv);                                               \
        aB = dotB * (wB * inv);                                               \
    }

        int t = 1;
        for (; t + 3 < h; t += 4) {
            FWD_STEP(t,     0)
            FWD_STEP(t + 1, 1)
            FWD_STEP(t + 2, 2)
            FWD_STEP(t + 3, 3)
        }
        for (; t < h; ++t) {
            const float sA = spA[(size_t)t * rs];
            const float sB = spB[(size_t)t * rs];
            const float wA = __expf(sA);
            const float wB = __expf(sB);
            {
                float* shp = &sh_ex[wid][(t - 1) & 1][0];
                shp[lane]      = aA;
                shp[32 + lane] = aB;
            }
            __syncwarp();
            float dotA, dotB, r;
            CRF_DOT48(shbase[(t - 1) & 1], TA, TB, dotA, dotB, r)
            const float inv = frcp(r);
            Mf += __logf(r);
            aA = dotA * (wA * inv);
            aB = dotB * (wB * inv);
        }
#undef FWD_STEP
    } else {
        // ===================== BACKWARD role ================================
        float Xb = 0.0f;
        for (int t = h + lane; t < L; t += 32) {
            const int tgt = target[t * BATCH + b];
            float v = scores[((size_t)t * BATCH + b) * NC + tgt]
                    + trans[target[(t - 1) * BATCH + b] * NC + tgt];
            Xb += v;
        }
#pragma unroll
        for (int o = 16; o > 0; o >>= 1)
            Xb += __shfl_xor_sync(FULL, Xb, o);

        // exp(E): TA/TB[j] = (E[c][2j], E[c][2j+1]) for c = cA / cB.
        unsigned long long TA[24], TB[24];
#pragma unroll
        for (int j = 0; j < 24; ++j) {
            TA[j] = pk2(__expf(trans[cA*NC + 2*j]), __expf(trans[cA*NC + 2*j+1]));
            TB[j] = v1 ? pk2(__expf(trans[cB*NC + 2*j]), __expf(trans[cB*NC + 2*j+1]))
                       : 0ull;
        }

        float Mb = 0.0f;
        float xA = 1.0f, xB = v1 ? 1.0f : 0.0f;
        const int nsteps = L - h;

        if (nsteps > 0) {
            float gA = __expf(spA[(size_t)(L - 1) * rs]);
            float gB = v1 ? __expf(spB[(size_t)(L - 1) * rs]) : 0.0f;

            float qA[4], qB[4];
#pragma unroll
            for (int kk = 0; kk < 4; ++kk) {
                int tt = L - 2 - kk; if (tt < 0) tt = 0;
                qA[kk] = spA[(size_t)tt * rs];
                qB[kk] = spB[(size_t)tt * rs];
            }

#define BWD_STEP(T, SLOT)                                                     \
    {                                                                         \
        const float sA = qA[SLOT];                                            \
        const float sB = qB[SLOT];                                            \
        qA[SLOT] = spA[(size_t)((T) - 5) * rs];                               \
        qB[SLOT] = spB[(size_t)((T) - 5) * rs];                               \
        const float wA = __expf(sA);                                          \
        const float wB = __expf(sB);                                          \
        {                                                                     \
            float* shp = &sh_ex[wid][(SLOT) & 1][0];                          \
            shp[lane]      = gA;                                              \
            shp[32 + lane] = gB;                                              \
        }                                                                     \
        __syncwarp();                                                         \
        float dotA, dotB, r;                                                  \
        CRF_DOT48(shbase[(SLOT) & 1], TA, TB, dotA, dotB, r)                  \
        const float inv = frcp(r);                                            \
        Mb += __logf(r);                                                      \
        xA = dotA * inv;                                                      \
        xB = dotB * inv;                                                      \
        gA = xA * wA;                                                         \
        gB = xB * wB;                                                         \
    }

            int t = L - 1;
            for (; t - 3 >= h && t >= 8; t -= 4) {
                BWD_STEP(t,     0)
                BWD_STEP(t - 1, 1)
                BWD_STEP(t - 2, 2)
                BWD_STEP(t - 3, 3)
            }
            for (; t >= h; --t) {
                int tm = t - 1; if (tm < 0) tm = 0;
                const float sA = spA[(size_t)tm * rs];
                const float sB = spB[(size_t)tm * rs];
                const float wA = __expf(sA);
                const float wB = __expf(sB);
                const int buf = (L - 1 - t) & 1;
                {
                    float* shp = &sh_ex[wid][buf][0];
                    shp[lane]      = gA;
                    shp[32 + lane] = gB;
                }
                __syncwarp();
                float dotA, dotB, r;
                CRF_DOT48(shbase[buf], TA, TB, dotA, dotB, r)
                const float inv = frcp(r);
                Mb += __logf(r);
                xA = dotA * inv;
                xB = dotB * inv;
                gA = xA * wA;
                gB = xB * wB;
            }
#undef BWD_STEP
        }

        sh_v[slot][lane]      = xA;
        sh_v[slot][32 + lane] = xB;   // lanes >= 16 write pad (48..63)
        if (lane == 0) { sh_mb[slot] = Mb; sh_xb[slot] = Xb; }
    }

    __syncthreads();

    if (isfwd) {
        // u_j v_j: class A on all lanes, class B (32+lane) on lanes < 16.
        float prod = aA * sh_v[slot][lane];
        if (v1) prod += aB * sh_v[slot][32 + lane];
#pragma unroll
        for (int o = 16; o > 0; o >>= 1)
            prod += __shfl_xor_sync(FULL, prod, o);
        if (lane == 0) {
            const float X    = Xpart + sh_xb[slot];
            const float logZ = Mf + sh_mb[slot] + __logf(prod);
            out[b]         = X;
            out[BATCH + b] = X - logZ;
        }
    }
}

// ---------------------------------------------------------------------------
extern "C" void kernel_launch(void* const* d_in, const int* in_sizes, int n_in,
                              void* d_out, int out_size)
{
    const float* scores  = (const float*)d_in[0];  // (1024, 512, 48) f32
    const int*   target  = (const int*)  d_in[1];  // (1024, 512) i32
    const int*   lengths = (const int*)  d_in[2];  // (512,) i32
    const float* trans   = (const float*)d_in[3];  // (48, 48) f32
    float* out = (float*)d_out;                    // (2, 512) f32

    crf_rank_kernel<<<1, BATCH>>>(lengths);
    crf_mitm_kernel<<<BATCH / 4, 256>>>(scores, target, lengths, trans, out);
}

// round 13
// speedup vs baseline: 1.0487x; 1.0487x over previous
#include <cuda_runtime.h>

#define SEQ   1024
#define BATCH 512
#define NC    48
#define FULL  0xffffffffu

__device__ int g_perm[BATCH];   // rank r -> batch index (descending length)

// ---- packed f32x2 helpers (sm_103a) ------------------------------------
static __device__ __forceinline__ unsigned long long pk2(float lo, float hi) {
    unsigned long long r;
    asm("mov.b64 %0, {%1,%2};" : "=l"(r) : "f"(lo), "f"(hi));
    return r;
}
static __device__ __forceinline__ unsigned long long fma2(
    unsigned long long a, unsigned long long b, unsigned long long c) {
    unsigned long long d;
    asm("fma.rn.f32x2 %0, %1, %2, %3;" : "=l"(d) : "l"(a), "l"(b), "l"(c));
    return d;
}
static __device__ __forceinline__ unsigned long long add2(
    unsigned long long a, unsigned long long b) {
    unsigned long long d;
    asm("add.rn.f32x2 %0, %1, %2;" : "=l"(d) : "l"(a), "l"(b));
    return d;
}
static __device__ __forceinline__ float hadd2(unsigned long long v) {
    float lo, hi;
    asm("mov.b64 {%0,%1}, %2;" : "=f"(lo), "=f"(hi) : "l"(v));
    return lo + hi;
}
static __device__ __forceinline__ float lo2(unsigned long long v) {
    float lo, hi;
    asm("mov.b64 {%0,%1}, %2;" : "=f"(lo), "=f"(hi) : "l"(v));
    return lo;
}
static __device__ __forceinline__ void lds16(
    unsigned long long& x, unsigned long long& y, unsigned int addr) {
    asm volatile("ld.shared.v2.u64 {%0,%1}, [%2];" : "=l"(x), "=l"(y) : "r"(addr));
}
static __device__ __forceinline__ float frcp(float x) {
    float r; asm("rcp.approx.f32 %0, %1;" : "=f"(r) : "f"(x)); return r;
}

// ---------------------------------------------------------------------------
// Rank prologue: counting rank by (length desc, index asc). Deterministic.
// ---------------------------------------------------------------------------
__global__ __launch_bounds__(BATCH) void crf_rank_kernel(
    const int* __restrict__ lengths)
{
    __shared__ int sl[BATCH];
    const int i = threadIdx.x;
    sl[i] = lengths[i];
    __syncthreads();
    const int Li = sl[i];
    int r = 0;
    for (int j = 0; j < BATCH; ++j) {
        const int Lj = sl[j];
        r += (Lj > Li) || (Lj == Li && j < i);
    }
    g_perm[r] = i;
}

// 36-fma2 / 12-LDS dot. Streams are parity-swapped:
//   P = sb + 96*par  (this lane's B-class rows AND half its A rows),
//   Q = sb + 96*(1-par) (the other half of its A rows).
// Constant tables are permuted per lane to match, so the B-side fma2s
// reuse the P registers directly — no 3rd LDS stream, no SELs.
// dotB is a pair-split half (joined via one shfl_xor, overlapping dotA's
// tree/mul/store tail). rfirst = exchanged[0].
#define CRF_DOTPQ(sbP, sbQ, parq, TAP, TAQ, TB, dotA, dotB, rfirst)           \
    {                                                                         \
        unsigned long long cA0=0ull,cA1=0ull,cA2=0ull,cA3=0ull;               \
        unsigned long long cB0=0ull,cB1=0ull;                                 \
        unsigned long long pf=0ull, qf=0ull;                                  \
        _Pragma("unroll")                                                     \
        for (int m = 0; m < 6; ++m) {                                         \
            unsigned long long p0,p1,q0,q1;                                   \
            lds16(p0, p1, (sbP) + 16u * m);                                   \
            lds16(q0, q1, (sbQ) + 16u * m);                                   \
            if (m == 0) { pf = p0; qf = q0; }                                 \
            cA0 = fma2(p0, TAP[2*m],   cA0);                                  \
            cA1 = fma2(p1, TAP[2*m+1], cA1);                                  \
            cA2 = fma2(q0, TAQ[2*m],   cA2);                                  \
            cA3 = fma2(q1, TAQ[2*m+1], cA3);                                  \
            cB0 = fma2(p0, TB[2*m],    cB0);                                  \
            cB1 = fma2(p1, TB[2*m+1],  cB1);                                  \
        }                                                                     \
        rfirst = lo2((parq) ? qf : pf);                                       \
        dotA = hadd2(add2(add2(cA0, cA1), add2(cA2, cA3)));                   \
        float _pb = hadd2(add2(cB0, cB1));                                    \
        dotB = _pb + __shfl_xor_sync(FULL, _pb, 1);                           \
    }

// ---------------------------------------------------------------------------
// Meet-in-the-middle CRF, contention-optimal partition:
// block k owns length-ranks {2k, 2k+1, 511-2k, 510-2k} (slots 0..3):
// two LONG + two TINY chains per block; each SMSP gets one long chain warp
// plus one tiny partner that retires almost immediately.
// Warp->(slot, role):  w0:(0,F) w1:(0,B) w2:(1,F) w3:(1,B)
//                      w4:(3,B) w5:(3,F) w6:(2,B) w7:(2,F)
// ---------------------------------------------------------------------------
__global__ __launch_bounds__(256, 1) void crf_mitm_kernel(
    const float* __restrict__ scores,
    const int*   __restrict__ target,
    const int*   __restrict__ lengths,
    const float* __restrict__ trans,
    float*       __restrict__ out)
{
    __shared__ float sh_ex[8][2][64];  // per-warp ping-pong exchange buffers
    __shared__ float sh_v[4][48];      // backward result vectors (per slot)
    __shared__ float sh_mb[4];         // backward Mlog
    __shared__ float sh_xb[4];         // backward X partial

    const int wid  = threadIdx.x >> 5;
    const int lane = threadIdx.x & 31;

    const int  slot  = (wid < 4) ? (wid >> 1) : (3 - ((wid - 4) >> 1));
    const bool isfwd = !((wid & 1) ^ ((wid >> 2) & 1));

    const int k    = blockIdx.x;
    const int rank = (slot == 0) ? (2 * k)
                   : (slot == 1) ? (2 * k + 1)
                   : (slot == 2) ? (511 - 2 * k)
                   :               (510 - 2 * k);
    const int b    = g_perm[rank];

    const int L = lengths[b];
    const int h = (L >= 2) ? (L >> 1) : 1;

    const int  cA  = lane;                 // owned class A (0..31)
    const int  cB  = 32 + (lane >> 1);     // shared class B (pair-split)
    const int  par = lane & 1;
    const int  rp  = 12 * par;             // P-stream pair offset for tables
    const int  rq  = 12 * (1 - par);       // Q-stream pair offset

    const float* spA = scores + (size_t)b * NC + cA;
    const float* spB = scores + (size_t)b * NC + cB;
    const size_t rs  = (size_t)BATCH * NC;

    unsigned int sbP[2], sbQ[2];
    {
        unsigned int s0 = (unsigned int)__cvta_generic_to_shared(&sh_ex[wid][0][0]);
        unsigned int s1 = (unsigned int)__cvta_generic_to_shared(&sh_ex[wid][1][0]);
        sbP[0] = s0 + 96u * (unsigned)par;        sbQ[0] = s0 + 96u * (unsigned)(1 - par);
        sbP[1] = s1 + 96u * (unsigned)par;        sbQ[1] = s1 + 96u * (unsigned)(1 - par);
    }

    float aA = 0.f, aB = 0.f, Mf = 0.f, Xpart = 0.f;

    if (isfwd) {
        // ===================== FORWARD role =================================
        for (int t = lane; t < h; t += 32) {
            const int tgt = target[t * BATCH + b];
            float v = scores[((size_t)t * BATCH + b) * NC + tgt];
            if (t > 0) v += trans[target[(t - 1) * BATCH + b] * NC + tgt];
            Xpart += v;
        }
#pragma unroll
        for (int o = 16; o > 0; o >>= 1)
            Xpart += __shfl_xor_sync(FULL, Xpart, o);

        // exp(E^T) column tables, permuted per lane parity:
        // pair q covers rows (2q, 2q+1); entry = (E[2q][c], E[2q+1][c]).
        unsigned long long TAP[12], TAQ[12], TB[12];
#pragma unroll
        for (int j = 0; j < 12; ++j) {
            int qp = j + rp, qq = j + rq;
            TAP[j] = pk2(__expf(trans[(2*qp)*NC + cA]), __expf(trans[(2*qp+1)*NC + cA]));
            TAQ[j] = pk2(__expf(trans[(2*qq)*NC + cA]), __expf(trans[(2*qq+1)*NC + cA]));
            TB[j]  = pk2(__expf(trans[(2*qp)*NC + cB]), __expf(trans[(2*qp+1)*NC + cB]));
        }

        aA = __expf(spA[0]);
        aB = __expf(spB[0]);

        float pA[4], pB[4];
#pragma unroll
        for (int kk = 0; kk < 4; ++kk) {
            pA[kk] = spA[(size_t)(1 + kk) * rs];
            pB[kk] = spB[(size_t)(1 + kk) * rs];
        }

#define FWD_STEP(T, SLOT)                                                     \
    {                                                                         \
        const float sA = pA[SLOT];                                            \
        const float sB = pB[SLOT];                                            \
        pA[SLOT] = spA[(size_t)((T) + 4) * rs];                               \
        pB[SLOT] = spB[(size_t)((T) + 4) * rs];                               \
        const float wA = __expf(sA);                                          \
        const float wB = __expf(sB);                                          \
        {                                                                     \
            float* shp = &sh_ex[wid][(SLOT) & 1][0];                          \
            shp[lane] = aA;                                                   \
            if (!par) shp[cB] = aB;                                           \
        }                                                                     \
        __syncwarp();                                                         \
        float dotA, dotB, r;                                                  \
        CRF_DOTPQ(sbP[(SLOT) & 1], sbQ[(SLOT) & 1], par, TAP, TAQ, TB,        \
                  dotA, dotB, r)                                              \
        const float inv = frcp(r);                                            \
        Mf += __logf(r);                                                      \
        aA = dotA * (wA * inv);                                               \
        aB = dotB * (wB * inv);                                               \
    }

        int t = 1;
        for (; t + 3 < h; t += 4) {
            FWD_STEP(t,     0)
            FWD_STEP(t + 1, 1)
            FWD_STEP(t + 2, 2)
            FWD_STEP(t + 3, 3)
        }
        for (; t < h; ++t) {
            const float sA = spA[(size_t)t * rs];
            const float sB = spB[(size_t)t * rs];
            const float wA = __expf(sA);
            const float wB = __expf(sB);
            {
                float* shp = &sh_ex[wid][(t - 1) & 1][0];
                shp[lane] = aA;
                if (!par) shp[cB] = aB;
            }
            __syncwarp();
            float dotA, dotB, r;
            CRF_DOTPQ(sbP[(t - 1) & 1], sbQ[(t - 1) & 1], par, TAP, TAQ, TB,
                      dotA, dotB, r)
            const float inv = frcp(r);
            Mf += __logf(r);
            aA = dotA * (wA * inv);
            aB = dotB * (wB * inv);
        }
#undef FWD_STEP
    } else {
        // ===================== BACKWARD role ================================
        float Xb = 0.0f;
        for (int t = h + lane; t < L; t += 32) {
            const int tgt = target[t * BATCH + b];
            float v = scores[((size_t)t * BATCH + b) * NC + tgt]
                    + trans[target[(t - 1) * BATCH + b] * NC + tgt];
            Xb += v;
        }
#pragma unroll
        for (int o = 16; o > 0; o >>= 1)
            Xb += __shfl_xor_sync(FULL, Xb, o);

        // exp(E) row tables (column-pair walk), permuted per lane parity.
        unsigned long long TAP[12], TAQ[12], TB[12];
#pragma unroll
        for (int j = 0; j < 12; ++j) {
            int qp = j + rp, qq = j + rq;
            TAP[j] = pk2(__expf(trans[cA*NC + 2*qp]), __expf(trans[cA*NC + 2*qp+1]));
            TAQ[j] = pk2(__expf(trans[cA*NC + 2*qq]), __expf(trans[cA*NC + 2*qq+1]));
            TB[j]  = pk2(__expf(trans[cB*NC + 2*qp]), __expf(trans[cB*NC + 2*qp+1]));
        }

        float Mb = 0.0f;
        float xA = 1.0f, xB = 1.0f;
        const int nsteps = L - h;

        if (nsteps > 0) {
            float gA = __expf(spA[(size_t)(L - 1) * rs]);
            float gB = __expf(spB[(size_t)(L - 1) * rs]);

            float qA[4], qB[4];
#pragma unroll
            for (int kk = 0; kk < 4; ++kk) {
                int tt = L - 2 - kk; if (tt < 0) tt = 0;
                qA[kk] = spA[(size_t)tt * rs];
                qB[kk] = spB[(size_t)tt * rs];
            }

#define BWD_STEP(T, SLOT)                                                     \
    {                                                                         \
        const float sA = qA[SLOT];                                            \
        const float sB = qB[SLOT];                                            \
        qA[SLOT] = spA[(size_t)((T) - 5) * rs];                               \
        qB[SLOT] = spB[(size_t)((T) - 5) * rs];                               \
        const float wA = __expf(sA);                                          \
        const float wB = __expf(sB);                                          \
        {                                                                     \
            float* shp = &sh_ex[wid][(SLOT) & 1][0];                          \
            shp[lane] = gA;                                                   \
            if (!par) shp[cB] = gB;                                           \
        }                                                                     \
        __syncwarp();                                                         \
        float dotA, dotB, r;                                                  \
        CRF_DOTPQ(sbP[(SLOT) & 1], sbQ[(SLOT) & 1], par, TAP, TAQ, TB,        \
                  dotA, dotB, r)                                              \
        const float inv = frcp(r);                                            \
        Mb += __logf(r);                                                      \
        xA = dotA * inv;                                                      \
        xB = dotB * inv;                                                      \
        gA = xA * wA;                                                         \
        gB = xB * wB;                                                         \
    }

            int t = L - 1;
            for (; t - 3 >= h && t >= 8; t -= 4) {
                BWD_STEP(t,     0)
                BWD_STEP(t - 1, 1)
                BWD_STEP(t - 2, 2)
                BWD_STEP(t - 3, 3)
            }
            for (; t >= h; --t) {
                int tm = t - 1; if (tm < 0) tm = 0;
                const float sA = spA[(size_t)tm * rs];
                const float sB = spB[(size_t)tm * rs];
                const float wA = __expf(sA);
                const float wB = __expf(sB);
                const int buf = (L - 1 - t) & 1;
                {
                    float* shp = &sh_ex[wid][buf][0];
                    shp[lane] = gA;
                    if (!par) shp[cB] = gB;
                }
                __syncwarp();
                float dotA, dotB, r;
                CRF_DOTPQ(sbP[buf], sbQ[buf], par, TAP, TAQ, TB, dotA, dotB, r)
                const float inv = frcp(r);
                Mb += __logf(r);
                xA = dotA * inv;
                xB = dotB * inv;
                gA = xA * wA;
                gB = xB * wB;
            }
#undef BWD_STEP
        }

        sh_v[slot][lane] = xA;
        if (!par) sh_v[slot][cB] = xB;
        if (lane == 0) { sh_mb[slot] = Mb; sh_xb[slot] = Xb; }
    }

    __syncthreads();

    if (isfwd) {
        // u[32+lane] lives as aB on lane 2*lane (valid for lane < 16)
        const float u32 = __shfl_sync(FULL, aB, (lane << 1) & 31);
        float prod = aA * sh_v[slot][lane];
        if (lane < 16) prod += u32 * sh_v[slot][32 + lane];
#pragma unroll
        for (int o = 16; o > 0; o >>= 1)
            prod += __shfl_xor_sync(FULL, prod, o);
        if (lane == 0) {
            const float X    = Xpart + sh_xb[slot];
            const float logZ = Mf + sh_mb[slot] + __logf(prod);
            out[b]         = X;
            out[BATCH + b] = X - logZ;
        }
    }
}

// ---------------------------------------------------------------------------
extern "C" void kernel_launch(void* const* d_in, const int* in_sizes, int n_in,
                              void* d_out, int out_size)
{
    const float* scores  = (const float*)d_in[0];  // (1024, 512, 48) f32
    const int*   target  = (const int*)  d_in[1];  // (1024, 512) i32
    const int*   lengths = (const int*)  d_in[2];  // (512,) i32
    const float* trans   = (const float*)d_in[3];  // (48, 48) f32
    float* out = (float*)d_out;                    // (2, 512) f32

    crf_rank_kernel<<<1, BATCH>>>(lengths);
    crf_mitm_kernel<<<BATCH / 4, 256>>>(scores, target, lengths, trans, out);
}

// round 14
// speedup vs baseline: 1.0531x; 1.0042x over previous
#include <cuda_runtime.h>

#define SEQ   1024
#define BATCH 512
#define NC    48
#define FULL  0xffffffffu

__device__ int g_perm[BATCH];   // rank r -> batch index (descending length)

// ---- packed f32x2 helpers (sm_103a) ------------------------------------
static __device__ __forceinline__ unsigned long long pk2(float lo, float hi) {
    unsigned long long r;
    asm("mov.b64 %0, {%1,%2};" : "=l"(r) : "f"(lo), "f"(hi));
    return r;
}
static __device__ __forceinline__ unsigned long long fma2(
    unsigned long long a, unsigned long long b, unsigned long long c) {
    unsigned long long d;
    asm("fma.rn.f32x2 %0, %1, %2, %3;" : "=l"(d) : "l"(a), "l"(b), "l"(c));
    return d;
}
static __device__ __forceinline__ unsigned long long add2(
    unsigned long long a, unsigned long long b) {
    unsigned long long d;
    asm("add.rn.f32x2 %0, %1, %2;" : "=l"(d) : "l"(a), "l"(b));
    return d;
}
static __device__ __forceinline__ float hadd2(unsigned long long v) {
    float lo, hi;
    asm("mov.b64 {%0,%1}, %2;" : "=f"(lo), "=f"(hi) : "l"(v));
    return lo + hi;
}
static __device__ __forceinline__ float lo2(unsigned long long v) {
    float lo, hi;
    asm("mov.b64 {%0,%1}, %2;" : "=f"(lo), "=f"(hi) : "l"(v));
    return lo;
}
// Ordered smem ops: memory clobbers keep STS before the LDS stream in the
// compiler; hardware keeps same-warp smem ops in issue order (converged
// warp, branch-free step body) -> no __syncwarp needed in the step.
static __device__ __forceinline__ void lds16(
    unsigned long long& x, unsigned long long& y, unsigned int addr) {
    asm volatile("ld.shared.v2.u64 {%0,%1}, [%2];"
                 : "=l"(x), "=l"(y) : "r"(addr) : "memory");
}
static __device__ __forceinline__ void sts32(unsigned int addr, float v) {
    asm volatile("st.shared.b32 [%0], %1;" :: "r"(addr), "f"(v) : "memory");
}
static __device__ __forceinline__ float frcp(float x) {
    float r; asm("rcp.approx.f32 %0, %1;" : "=f"(r) : "f"(x)); return r;
}

// ---------------------------------------------------------------------------
// Rank prologue: counting rank by (length desc, index asc). Deterministic.
// ---------------------------------------------------------------------------
__global__ __launch_bounds__(BATCH) void crf_rank_kernel(
    const int* __restrict__ lengths)
{
    __shared__ int sl[BATCH];
    const int i = threadIdx.x;
    sl[i] = lengths[i];
    __syncthreads();
    const int Li = sl[i];
    int r = 0;
    for (int j = 0; j < BATCH; ++j) {
        const int Lj = sl[j];
        r += (Lj > Li) || (Lj == Li && j < i);
    }
    g_perm[r] = i;
}

// 36-fma2 / 12-LDS dot with parity-swapped streams (R13 version).
#define CRF_DOTPQ(sbP, sbQ, parq, TAP, TAQ, TB, dotA, dotB, rfirst)           \
    {                                                                         \
        unsigned long long cA0=0ull,cA1=0ull,cA2=0ull,cA3=0ull;               \
        unsigned long long cB0=0ull,cB1=0ull;                                 \
        unsigned long long pf=0ull, qf=0ull;                                  \
        _Pragma("unroll")                                                     \
        for (int m = 0; m < 6; ++m) {                                         \
            unsigned long long p0,p1,q0,q1;                                   \
            lds16(p0, p1, (sbP) + 16u * m);                                   \
            lds16(q0, q1, (sbQ) + 16u * m);                                   \
            if (m == 0) { pf = p0; qf = q0; }                                 \
            cA0 = fma2(p0, TAP[2*m],   cA0);                                  \
            cA1 = fma2(p1, TAP[2*m+1], cA1);                                  \
            cA2 = fma2(q0, TAQ[2*m],   cA2);                                  \
            cA3 = fma2(q1, TAQ[2*m+1], cA3);                                  \
            cB0 = fma2(p0, TB[2*m],    cB0);                                  \
            cB1 = fma2(p1, TB[2*m+1],  cB1);                                  \
        }                                                                     \
        rfirst = lo2((parq) ? qf : pf);                                       \
        dotA = hadd2(add2(add2(cA0, cA1), add2(cA2, cA3)));                   \
        float _pb = hadd2(add2(cB0, cB1));                                    \
        dotB = _pb + __shfl_xor_sync(FULL, _pb, 1);                           \
    }

// ---------------------------------------------------------------------------
// Meet-in-the-middle CRF; block k owns ranks {2k, 2k+1, 511-2k, 510-2k}.
// Warp->(slot, role):  w0:(0,F) w1:(0,B) w2:(1,F) w3:(1,B)
//                      w4:(3,B) w5:(3,F) w6:(2,B) w7:(2,F)
// R14: no per-step __syncwarp (converged-warp LSU ordering + asm clobbers);
// renormalization every 2nd step (delayed renorm is cadence-agnostic).
// ---------------------------------------------------------------------------
__global__ __launch_bounds__(256, 1) void crf_mitm_kernel(
    const float* __restrict__ scores,
    const int*   __restrict__ target,
    const int*   __restrict__ lengths,
    const float* __restrict__ trans,
    float*       __restrict__ out)
{
    __shared__ float sh_ex[8][2][64];  // per-warp ping-pong exchange buffers
    __shared__ float sh_v[4][48];      // backward result vectors (per slot)
    __shared__ float sh_mb[4];         // backward Mlog
    __shared__ float sh_xb[4];         // backward X partial

    const int wid  = threadIdx.x >> 5;
    const int lane = threadIdx.x & 31;

    const int  slot  = (wid < 4) ? (wid >> 1) : (3 - ((wid - 4) >> 1));
    const bool isfwd = !((wid & 1) ^ ((wid >> 2) & 1));

    const int k    = blockIdx.x;
    const int rank = (slot == 0) ? (2 * k)
                   : (slot == 1) ? (2 * k + 1)
                   : (slot == 2) ? (511 - 2 * k)
                   :               (510 - 2 * k);
    const int b    = g_perm[rank];

    const int L = lengths[b];
    const int h = (L >= 2) ? (L >> 1) : 1;

    const int  cA  = lane;                 // owned class A (0..31)
    const int  cB  = 32 + (lane >> 1);     // shared class B (pair-split)
    const int  par = lane & 1;
    const int  rp  = 12 * par;             // P-stream pair offset for tables
    const int  rq  = 12 * (1 - par);       // Q-stream pair offset

    const float* spA = scores + (size_t)b * NC + cA;
    const float* spB = scores + (size_t)b * NC + cB;
    const size_t rs  = (size_t)BATCH * NC;

    unsigned int sbP[2], sbQ[2], stA[2], stB[2];
    {
        unsigned int s0 = (unsigned int)__cvta_generic_to_shared(&sh_ex[wid][0][0]);
        unsigned int s1 = (unsigned int)__cvta_generic_to_shared(&sh_ex[wid][1][0]);
        sbP[0] = s0 + 96u * (unsigned)par;   sbQ[0] = s0 + 96u * (unsigned)(1 - par);
        sbP[1] = s1 + 96u * (unsigned)par;   sbQ[1] = s1 + 96u * (unsigned)(1 - par);
        stA[0] = s0 + 4u * (unsigned)lane;   stA[1] = s1 + 4u * (unsigned)lane;
        stB[0] = s0 + 4u * (unsigned)cB;     stB[1] = s1 + 4u * (unsigned)cB;
    }

    float aA = 0.f, aB = 0.f, Mf = 0.f, Xpart = 0.f;

    if (isfwd) {
        // ===================== FORWARD role =================================
        for (int t = lane; t < h; t += 32) {
            const int tgt = target[t * BATCH + b];
            float v = scores[((size_t)t * BATCH + b) * NC + tgt];
            if (t > 0) v += trans[target[(t - 1) * BATCH + b] * NC + tgt];
            Xpart += v;
        }
#pragma unroll
        for (int o = 16; o > 0; o >>= 1)
            Xpart += __shfl_xor_sync(FULL, Xpart, o);

        // exp(E^T) column tables, permuted per lane parity.
        unsigned long long TAP[12], TAQ[12], TB[12];
#pragma unroll
        for (int j = 0; j < 12; ++j) {
            int qp = j + rp, qq = j + rq;
            TAP[j] = pk2(__expf(trans[(2*qp)*NC + cA]), __expf(trans[(2*qp+1)*NC + cA]));
            TAQ[j] = pk2(__expf(trans[(2*qq)*NC + cA]), __expf(trans[(2*qq+1)*NC + cA]));
            TB[j]  = pk2(__expf(trans[(2*qp)*NC + cB]), __expf(trans[(2*qp+1)*NC + cB]));
        }

        aA = __expf(spA[0]);
        aB = __expf(spB[0]);

        float pA[4], pB[4];
#pragma unroll
        for (int kk = 0; kk < 4; ++kk) {
            pA[kk] = spA[(size_t)(1 + kk) * rs];
            pB[kk] = spB[(size_t)(1 + kk) * rs];
        }

// RN = 1: renormalize by r = alpha_prev[0] (and log-compensate). RN = 0:
// plain step (growth carried in alpha; exactly compensated at next renorm
// or by the final log-sum). Cadence-agnostic identity.
#define FWD_STEP(T, SLOT, RN)                                                 \
    {                                                                         \
        const float sA = pA[SLOT];                                            \
        const float sB = pB[SLOT];                                            \
        pA[SLOT] = spA[(size_t)((T) + 4) * rs];                               \
        pB[SLOT] = spB[(size_t)((T) + 4) * rs];                               \
        const float wA = __expf(sA);                                          \
        const float wB = __expf(sB);                                          \
        sts32(stA[(SLOT) & 1], aA);                                           \
        if (!par) sts32(stB[(SLOT) & 1], aB);                                 \
        float dotA, dotB, r;                                                  \
        CRF_DOTPQ(sbP[(SLOT) & 1], sbQ[(SLOT) & 1], par, TAP, TAQ, TB,        \
                  dotA, dotB, r)                                              \
        if (RN) {                                                             \
            const float inv = frcp(r);                                        \
            Mf += __logf(r);                                                  \
            aA = dotA * (wA * inv);                                           \
            aB = dotB * (wB * inv);                                           \
        } else {                                                              \
            aA = dotA * wA;                                                   \
            aB = dotB * wB;                                                   \
        }                                                                     \
    }

        int t = 1;
        for (; t + 3 < h; t += 4) {
            FWD_STEP(t,     0, 1)
            FWD_STEP(t + 1, 1, 0)
            FWD_STEP(t + 2, 2, 1)
            FWD_STEP(t + 3, 3, 0)
        }
        for (; t < h; ++t) {   // tail <=3: direct loads, renorm every step
            const float sA = spA[(size_t)t * rs];
            const float sB = spB[(size_t)t * rs];
            const float wA = __expf(sA);
            const float wB = __expf(sB);
            sts32(stA[(t - 1) & 1], aA);
            if (!par) sts32(stB[(t - 1) & 1], aB);
            float dotA, dotB, r;
            CRF_DOTPQ(sbP[(t - 1) & 1], sbQ[(t - 1) & 1], par, TAP, TAQ, TB,
                      dotA, dotB, r)
            const float inv = frcp(r);
            Mf += __logf(r);
            aA = dotA * (wA * inv);
            aB = dotB * (wB * inv);
        }
#undef FWD_STEP
    } else {
        // ===================== BACKWARD role ================================
        float Xb = 0.0f;
        for (int t = h + lane; t < L; t += 32) {
            const int tgt = target[t * BATCH + b];
            float v = scores[((size_t)t * BATCH + b) * NC + tgt]
                    + trans[target[(t - 1) * BATCH + b] * NC + tgt];
            Xb += v;
        }
#pragma unroll
        for (int o = 16; o > 0; o >>= 1)
            Xb += __shfl_xor_sync(FULL, Xb, o);

        // exp(E) row tables (column-pair walk), permuted per lane parity.
        unsigned long long TAP[12], TAQ[12], TB[12];
#pragma unroll
        for (int j = 0; j < 12; ++j) {
            int qp = j + rp, qq = j + rq;
            TAP[j] = pk2(__expf(trans[cA*NC + 2*qp]), __expf(trans[cA*NC + 2*qp+1]));
            TAQ[j] = pk2(__expf(trans[cA*NC + 2*qq]), __expf(trans[cA*NC + 2*qq+1]));
            TB[j]  = pk2(__expf(trans[cB*NC + 2*qp]), __expf(trans[cB*NC + 2*qp+1]));
        }

        float Mb = 0.0f;
        float xA = 1.0f, xB = 1.0f;
        const int nsteps = L - h;

        if (nsteps > 0) {
            float gA = __expf(spA[(size_t)(L - 1) * rs]);
            float gB = __expf(spB[(size_t)(L - 1) * rs]);

            float qA[4], qB[4];
#pragma unroll
            for (int kk = 0; kk < 4; ++kk) {
                int tt = L - 2 - kk; if (tt < 0) tt = 0;
                qA[kk] = spA[(size_t)tt * rs];
                qB[kk] = spB[(size_t)tt * rs];
            }

#define BWD_STEP(T, SLOT, RN)                                                 \
    {                                                                         \
        const float sA = qA[SLOT];                                            \
        const float sB = qB[SLOT];                                            \
        qA[SLOT] = spA[(size_t)((T) - 5) * rs];                               \
        qB[SLOT] = spB[(size_t)((T) - 5) * rs];                               \
        const float wA = __expf(sA);                                          \
        const float wB = __expf(sB);                                          \
        sts32(stA[(SLOT) & 1], gA);                                           \
        if (!par) sts32(stB[(SLOT) & 1], gB);                                 \
        float dotA, dotB, r;                                                  \
        CRF_DOTPQ(sbP[(SLOT) & 1], sbQ[(SLOT) & 1], par, TAP, TAQ, TB,        \
                  dotA, dotB, r)                                              \
        if (RN) {                                                             \
            const float inv = frcp(r);                                        \
            Mb += __logf(r);                                                  \
            xA = dotA * inv;                                                  \
            xB = dotB * inv;                                                  \
        } else {                                                              \
            xA = dotA;                                                        \
            xB = dotB;                                                        \
        }                                                                     \
        gA = xA * wA;                                                         \
        gB = xB * wB;                                                         \
    }

            int t = L - 1;
            for (; t - 3 >= h && t >= 8; t -= 4) {
                BWD_STEP(t,     0, 1)
                BWD_STEP(t - 1, 1, 0)
                BWD_STEP(t - 2, 2, 1)
                BWD_STEP(t - 3, 3, 0)
            }
            for (; t >= h; --t) {  // tail: direct clamped loads, renorm each
                int tm = t - 1; if (tm < 0) tm = 0;
                const float sA = spA[(size_t)tm * rs];
                const float sB = spB[(size_t)tm * rs];
                const float wA = __expf(sA);
                const float wB = __expf(sB);
                const int buf = (L - 1 - t) & 1;
                sts32(stA[buf], gA);
                if (!par) sts32(stB[buf], gB);
                float dotA, dotB, r;
                CRF_DOTPQ(sbP[buf], sbQ[buf], par, TAP, TAQ, TB, dotA, dotB, r)
                const float inv = frcp(r);
                Mb += __logf(r);
                xA = dotA * inv;
                xB = dotB * inv;
                gA = xA * wA;
                gB = xB * wB;
            }
#undef BWD_STEP
        }

        sh_v[slot][lane] = xA;
        if (!par) sh_v[slot][cB] = xB;
        if (lane == 0) { sh_mb[slot] = Mb; sh_xb[slot] = Xb; }
    }

    __syncthreads();

    if (isfwd) {
        // u[32+lane] lives as aB on lane 2*lane (valid for lane < 16)
        const float u32 = __shfl_sync(FULL, aB, (lane << 1) & 31);
        float prod = aA * sh_v[slot][lane];
        if (lane < 16) prod += u32 * sh_v[slot][32 + lane];
#pragma unroll
        for (int o = 16; o > 0; o >>= 1)
            prod += __shfl_xor_sync(FULL, prod, o);
        if (lane == 0) {
            const float X    = Xpart + sh_xb[slot];
            const float logZ = Mf + sh_mb[slot] + __logf(prod);
            out[b]         = X;
            out[BATCH + b] = X - logZ;
        }
    }
}

// ---------------------------------------------------------------------------
extern "C" void kernel_launch(void* const* d_in, const int* in_sizes, int n_in,
                              void* d_out, int out_size)
{
    const float* scores  = (const float*)d_in[0];  // (1024, 512, 48) f32
    const int*   target  = (const int*)  d_in[1];  // (1024, 512) i32
    const int*   lengths = (const int*)  d_in[2];  // (512,) i32
    const float* trans   = (const float*)d_in[3];  // (48, 48) f32
    float* out = (float*)d_out;                    // (2, 512) f32

    crf_rank_kernel<<<1, BATCH>>>(lengths);
    crf_mitm_kernel<<<BATCH / 4, 256>>>(scores, target, lengths, trans, out);
}

// round 15
// speedup vs baseline: 1.0858x; 1.0310x over previous
#include <cuda_runtime.h>

#define SEQ   1024
#define BATCH 512
#define NC    48
#define FULL  0xffffffffu

__device__ int g_perm[BATCH];   // rank r -> batch index (descending length)

// ---- packed f32x2 helpers (sm_103a) ------------------------------------
static __device__ __forceinline__ unsigned long long pk2(float lo, float hi) {
    unsigned long long r;
    asm("mov.b64 %0, {%1,%2};" : "=l"(r) : "f"(lo), "f"(hi));
    return r;
}
static __device__ __forceinline__ unsigned long long fma2(
    unsigned long long a, unsigned long long b, unsigned long long c) {
    unsigned long long d;
    asm("fma.rn.f32x2 %0, %1, %2, %3;" : "=l"(d) : "l"(a), "l"(b), "l"(c));
    return d;
}
static __device__ __forceinline__ unsigned long long add2(
    unsigned long long a, unsigned long long b) {
    unsigned long long d;
    asm("add.rn.f32x2 %0, %1, %2;" : "=l"(d) : "l"(a), "l"(b));
    return d;
}
static __device__ __forceinline__ float hadd2(unsigned long long v) {
    float lo, hi;
    asm("mov.b64 {%0,%1}, %2;" : "=f"(lo), "=f"(hi) : "l"(v));
    return lo + hi;
}
static __device__ __forceinline__ float lo2(unsigned long long v) {
    float lo, hi;
    asm("mov.b64 {%0,%1}, %2;" : "=f"(lo), "=f"(hi) : "l"(v));
    return lo;
}
// Ordered smem ops: memory clobbers keep STS before the LDS stream in the
// compiler; hardware keeps same-warp smem ops in issue order (converged
// warp, branch-free step body) -> no __syncwarp needed in the step.
static __device__ __forceinline__ void lds16(
    unsigned long long& x, unsigned long long& y, unsigned int addr) {
    asm volatile("ld.shared.v2.u64 {%0,%1}, [%2];"
                 : "=l"(x), "=l"(y) : "r"(addr) : "memory");
}
static __device__ __forceinline__ void sts32(unsigned int addr, float v) {
    asm volatile("st.shared.b32 [%0], %1;" :: "r"(addr), "f"(v) : "memory");
}
static __device__ __forceinline__ float frcp(float x) {
    float r; asm("rcp.approx.f32 %0, %1;" : "=f"(r) : "f"(x)); return r;
}

// ---------------------------------------------------------------------------
// Rank prologue: counting rank by (length desc, index asc). Deterministic.
// ---------------------------------------------------------------------------
__global__ __launch_bounds__(BATCH) void crf_rank_kernel(
    const int* __restrict__ lengths)
{
    __shared__ int sl[BATCH];
    const int i = threadIdx.x;
    sl[i] = lengths[i];
    __syncthreads();
    const int Li = sl[i];
    int r = 0;
    for (int j = 0; j < BATCH; ++j) {
        const int Lj = sl[j];
        r += (Lj > Li) || (Lj == Li && j < i);
    }
    g_perm[r] = i;
}

// 36-fma2 / 12-LDS dot with parity-swapped streams (R13/R14 version).
#define CRF_DOTPQ(sbP, sbQ, parq, TAP, TAQ, TB, dotA, dotB, rfirst)           \
    {                                                                         \
        unsigned long long cA0=0ull,cA1=0ull,cA2=0ull,cA3=0ull;               \
        unsigned long long cB0=0ull,cB1=0ull;                                 \
        unsigned long long pf=0ull, qf=0ull;                                  \
        _Pragma("unroll")                                                     \
        for (int m = 0; m < 6; ++m) {                                         \
            unsigned long long p0,p1,q0,q1;                                   \
            lds16(p0, p1, (sbP) + 16u * m);                                   \
            lds16(q0, q1, (sbQ) + 16u * m);                                   \
            if (m == 0) { pf = p0; qf = q0; }                                 \
            cA0 = fma2(p0, TAP[2*m],   cA0);                                  \
            cA1 = fma2(p1, TAP[2*m+1], cA1);                                  \
            cA2 = fma2(q0, TAQ[2*m],   cA2);                                  \
            cA3 = fma2(q1, TAQ[2*m+1], cA3);                                  \
            cB0 = fma2(p0, TB[2*m],    cB0);                                  \
            cB1 = fma2(p1, TB[2*m+1],  cB1);                                  \
        }                                                                     \
        rfirst = lo2((parq) ? qf : pf);                                       \
        dotA = hadd2(add2(add2(cA0, cA1), add2(cA2, cA3)));                   \
        float _pb = hadd2(add2(cB0, cB1));                                    \
        dotB = _pb + __shfl_xor_sync(FULL, _pb, 1);                           \
    }

// ---------------------------------------------------------------------------
// Meet-in-the-middle CRF; block k owns ranks {2k, 2k+1, 511-2k, 510-2k}.
// Warp->(slot, role):  w0:(0,F) w1:(0,B) w2:(1,F) w3:(1,B)
//                      w4:(3,B) w5:(3,F) w6:(2,B) w7:(2,F)
// R15: LONG chains (slots 0,1 = w0..w3) do NO X work. Their X halves are
// computed by the short-slot warps AFTER those finish their own chains:
//   w5 -> Xf[slot0], w4 -> Xb[slot0], w7 -> Xf[slot1], w6 -> Xb[slot1].
// Identical t-partition and lane striding -> bit-identical X values.
// ---------------------------------------------------------------------------
__global__ __launch_bounds__(256, 1) void crf_mitm_kernel(
    const float* __restrict__ scores,
    const int*   __restrict__ target,
    const int*   __restrict__ lengths,
    const float* __restrict__ trans,
    float*       __restrict__ out)
{
    __shared__ float sh_ex[8][2][64];  // per-warp ping-pong exchange buffers
    __shared__ float sh_v[4][48];      // backward result vectors (per slot)
    __shared__ float sh_mb[4];         // backward Mlog
    __shared__ float sh_xb[4];         // X bwd-half  [h, L)
    __shared__ float sh_xf[4];         // X fwd-half  [0, h)  (slots 0,1 only)

    const int wid  = threadIdx.x >> 5;
    const int lane = threadIdx.x & 31;

    const int  slot  = (wid < 4) ? (wid >> 1) : (3 - ((wid - 4) >> 1));
    const bool isfwd = !((wid & 1) ^ ((wid >> 2) & 1));

    const int k    = blockIdx.x;
    const int rank = (slot == 0) ? (2 * k)
                   : (slot == 1) ? (2 * k + 1)
                   : (slot == 2) ? (511 - 2 * k)
                   :               (510 - 2 * k);
    const int b    = g_perm[rank];

    const int L = lengths[b];
    const int h = (L >= 2) ? (L >> 1) : 1;

    const int  cA  = lane;                 // owned class A (0..31)
    const int  cB  = 32 + (lane >> 1);     // shared class B (pair-split)
    const int  par = lane & 1;
    const int  rp  = 12 * par;             // P-stream pair offset for tables
    const int  rq  = 12 * (1 - par);       // Q-stream pair offset

    const float* spA = scores + (size_t)b * NC + cA;
    const float* spB = scores + (size_t)b * NC + cB;
    const size_t rs  = (size_t)BATCH * NC;

    unsigned int sbP[2], sbQ[2], stA[2], stB[2];
    {
        unsigned int s0 = (unsigned int)__cvta_generic_to_shared(&sh_ex[wid][0][0]);
        unsigned int s1 = (unsigned int)__cvta_generic_to_shared(&sh_ex[wid][1][0]);
        sbP[0] = s0 + 96u * (unsigned)par;   sbQ[0] = s0 + 96u * (unsigned)(1 - par);
        sbP[1] = s1 + 96u * (unsigned)par;   sbQ[1] = s1 + 96u * (unsigned)(1 - par);
        stA[0] = s0 + 4u * (unsigned)lane;   stA[1] = s1 + 4u * (unsigned)lane;
        stB[0] = s0 + 4u * (unsigned)cB;     stB[1] = s1 + 4u * (unsigned)cB;
    }

    float aA = 0.f, aB = 0.f, Mf = 0.f, Xpart = 0.f;

    if (isfwd) {
        // ===================== FORWARD role =================================
        // Own X fwd-half: SHORT slots only (long slots offloaded).
        if (wid >= 4) {
            for (int t = lane; t < h; t += 32) {
                const int tgt = target[t * BATCH + b];
                float v = scores[((size_t)t * BATCH + b) * NC + tgt];
                if (t > 0) v += trans[target[(t - 1) * BATCH + b] * NC + tgt];
                Xpart += v;
            }
#pragma unroll
            for (int o = 16; o > 0; o >>= 1)
                Xpart += __shfl_xor_sync(FULL, Xpart, o);
        }

        // exp(E^T) column tables, permuted per lane parity.
        unsigned long long TAP[12], TAQ[12], TB[12];
#pragma unroll
        for (int j = 0; j < 12; ++j) {
            int qp = j + rp, qq = j + rq;
            TAP[j] = pk2(__expf(trans[(2*qp)*NC + cA]), __expf(trans[(2*qp+1)*NC + cA]));
            TAQ[j] = pk2(__expf(trans[(2*qq)*NC + cA]), __expf(trans[(2*qq+1)*NC + cA]));
            TB[j]  = pk2(__expf(trans[(2*qp)*NC + cB]), __expf(trans[(2*qp+1)*NC + cB]));
        }

        aA = __expf(spA[0]);
        aB = __expf(spB[0]);

        float pA[4], pB[4];
#pragma unroll
        for (int kk = 0; kk < 4; ++kk) {
            pA[kk] = spA[(size_t)(1 + kk) * rs];
            pB[kk] = spB[(size_t)(1 + kk) * rs];
        }

// RN = 1: renormalize by r = alpha_prev[0] (and log-compensate). RN = 0:
// plain step. Cadence-agnostic identity.
#define FWD_STEP(T, SLOT, RN)                                                 \
    {                                                                         \
        const float sA = pA[SLOT];                                            \
        const float sB = pB[SLOT];                                            \
        pA[SLOT] = spA[(size_t)((T) + 4) * rs];                               \
        pB[SLOT] = spB[(size_t)((T) + 4) * rs];                               \
        const float wA = __expf(sA);                                          \
        const float wB = __expf(sB);                                          \
        sts32(stA[(SLOT) & 1], aA);                                           \
        if (!par) sts32(stB[(SLOT) & 1], aB);                                 \
        float dotA, dotB, r;                                                  \
        CRF_DOTPQ(sbP[(SLOT) & 1], sbQ[(SLOT) & 1], par, TAP, TAQ, TB,        \
                  dotA, dotB, r)                                              \
        if (RN) {                                                             \
            const float inv = frcp(r);                                        \
            Mf += __logf(r);                                                  \
            aA = dotA * (wA * inv);                                           \
            aB = dotB * (wB * inv);                                           \
        } else {                                                              \
            aA = dotA * wA;                                                   \
            aB = dotB * wB;                                                   \
        }                                                                     \
    }

        int t = 1;
        for (; t + 3 < h; t += 4) {
            FWD_STEP(t,     0, 1)
            FWD_STEP(t + 1, 1, 0)
            FWD_STEP(t + 2, 2, 1)
            FWD_STEP(t + 3, 3, 0)
        }
        for (; t < h; ++t) {   // tail <=3: direct loads, renorm every step
            const float sA = spA[(size_t)t * rs];
            const float sB = spB[(size_t)t * rs];
            const float wA = __expf(sA);
            const float wB = __expf(sB);
            sts32(stA[(t - 1) & 1], aA);
            if (!par) sts32(stB[(t - 1) & 1], aB);
            float dotA, dotB, r;
            CRF_DOTPQ(sbP[(t - 1) & 1], sbQ[(t - 1) & 1], par, TAP, TAQ, TB,
                      dotA, dotB, r)
            const float inv = frcp(r);
            Mf += __logf(r);
            aA = dotA * (wA * inv);
            aB = dotB * (wB * inv);
        }
#undef FWD_STEP
    } else {
        // ===================== BACKWARD role ================================
        // Own X bwd-half: SHORT slots only.
        if (wid >= 4) {
            float Xb = 0.0f;
            for (int t = h + lane; t < L; t += 32) {
                const int tgt = target[t * BATCH + b];
                float v = scores[((size_t)t * BATCH + b) * NC + tgt]
                        + trans[target[(t - 1) * BATCH + b] * NC + tgt];
                Xb += v;
            }
#pragma unroll
            for (int o = 16; o > 0; o >>= 1)
                Xb += __shfl_xor_sync(FULL, Xb, o);
            if (lane == 0) sh_xb[slot] = Xb;
        }

        // exp(E) row tables (column-pair walk), permuted per lane parity.
        unsigned long long TAP[12], TAQ[12], TB[12];
#pragma unroll
        for (int j = 0; j < 12; ++j) {
            int qp = j + rp, qq = j + rq;
            TAP[j] = pk2(__expf(trans[cA*NC + 2*qp]), __expf(trans[cA*NC + 2*qp+1]));
            TAQ[j] = pk2(__expf(trans[cA*NC + 2*qq]), __expf(trans[cA*NC + 2*qq+1]));
            TB[j]  = pk2(__expf(trans[cB*NC + 2*qp]), __expf(trans[cB*NC + 2*qp+1]));
        }

        float Mb = 0.0f;
        float xA = 1.0f, xB = 1.0f;
        const int nsteps = L - h;

        if (nsteps > 0) {
            float gA = __expf(spA[(size_t)(L - 1) * rs]);
            float gB = __expf(spB[(size_t)(L - 1) * rs]);

            float qA[4], qB[4];
#pragma unroll
            for (int kk = 0; kk < 4; ++kk) {
                int tt = L - 2 - kk; if (tt < 0) tt = 0;
                qA[kk] = spA[(size_t)tt * rs];
                qB[kk] = spB[(size_t)tt * rs];
            }

#define BWD_STEP(T, SLOT, RN)                                                 \
    {                                                                         \
        const float sA = qA[SLOT];                                            \
        const float sB = qB[SLOT];                                            \
        qA[SLOT] = spA[(size_t)((T) - 5) * rs];                               \
        qB[SLOT] = spB[(size_t)((T) - 5) * rs];                               \
        const float wA = __expf(sA);                                          \
        const float wB = __expf(sB);                                          \
        sts32(stA[(SLOT) & 1], gA);                                           \
        if (!par) sts32(stB[(SLOT) & 1], gB);                                 \
        float dotA, dotB, r;                                                  \
        CRF_DOTPQ(sbP[(SLOT) & 1], sbQ[(SLOT) & 1], par, TAP, TAQ, TB,        \
                  dotA, dotB, r)                                              \
        if (RN) {                                                             \
            const float inv = frcp(r);                                        \
            Mb += __logf(r);                                                  \
            xA = dotA * inv;                                                  \
            xB = dotB * inv;                                                  \
        } else {                                                              \
            xA = dotA;                                                        \
            xB = dotB;                                                        \
        }                                                                     \
        gA = xA * wA;                                                         \
        gB = xB * wB;                                                         \
    }

            int t = L - 1;
            for (; t - 3 >= h && t >= 8; t -= 4) {
                BWD_STEP(t,     0, 1)
                BWD_STEP(t - 1, 1, 0)
                BWD_STEP(t - 2, 2, 1)
                BWD_STEP(t - 3, 3, 0)
            }
            for (; t >= h; --t) {  // tail: direct clamped loads, renorm each
                int tm = t - 1; if (tm < 0) tm = 0;
                const float sA = spA[(size_t)tm * rs];
                const float sB = spB[(size_t)tm * rs];
                const float wA = __expf(sA);
                const float wB = __expf(sB);
                const int buf = (L - 1 - t) & 1;
                sts32(stA[buf], gA);
                if (!par) sts32(stB[buf], gB);
                float dotA, dotB, r;
                CRF_DOTPQ(sbP[buf], sbQ[buf], par, TAP, TAQ, TB, dotA, dotB, r)
                const float inv = frcp(r);
                Mb += __logf(r);
                xA = dotA * inv;
                xB = dotB * inv;
                gA = xA * wA;
                gB = xB * wB;
            }
#undef BWD_STEP
        }

        sh_v[slot][lane] = xA;
        if (!par) sh_v[slot][cB] = xB;
        if (lane == 0) sh_mb[slot] = Mb;
    }

    // ------ Offloaded X for the LONG slots (short-slot warps, post-chain) ---
    if (wid >= 4) {
        const int xslot = (wid < 6) ? 0 : 1;             // w4,w5 -> slot0; w6,w7 -> slot1
        const int xrank = (xslot == 0) ? (2 * k) : (2 * k + 1);
        const int xb_   = g_perm[xrank];
        const int xL    = lengths[xb_];
        const int xh    = (xL >= 2) ? (xL >> 1) : 1;
        float xs = 0.0f;
        if (isfwd) {        // w5, w7: fwd half [0, xh)
            for (int t = lane; t < xh; t += 32) {
                const int tgt = target[t * BATCH + xb_];
                float v = scores[((size_t)t * BATCH + xb_) * NC + tgt];
                if (t > 0) v += trans[target[(t - 1) * BATCH + xb_] * NC + tgt];
                xs += v;
            }
#pragma unroll
            for (int o = 16; o > 0; o >>= 1)
                xs += __shfl_xor_sync(FULL, xs, o);
            if (lane == 0) sh_xf[xslot] = xs;
        } else {            // w4, w6: bwd half [xh, xL)
            for (int t = xh + lane; t < xL; t += 32) {
                const int tgt = target[t * BATCH + xb_];
                float v = scores[((size_t)t * BATCH + xb_) * NC + tgt]
                        + trans[target[(t - 1) * BATCH + xb_] * NC + tgt];
                xs += v;
            }
#pragma unroll
            for (int o = 16; o > 0; o >>= 1)
                xs += __shfl_xor_sync(FULL, xs, o);
            if (lane == 0) sh_xb[xslot] = xs;
        }
    }

    __syncthreads();

    if (isfwd) {
        // u[32+lane] lives as aB on lane 2*lane (valid for lane < 16)
        const float u32 = __shfl_sync(FULL, aB, (lane << 1) & 31);
        float prod = aA * sh_v[slot][lane];
        if (lane < 16) prod += u32 * sh_v[slot][32 + lane];
#pragma unroll
        for (int o = 16; o > 0; o >>= 1)
            prod += __shfl_xor_sync(FULL, prod, o);
        if (lane == 0) {
            const float Xf   = (slot < 2) ? sh_xf[slot] : Xpart;
            const float X    = Xf + sh_xb[slot];
            const float logZ = Mf + sh_mb[slot] + __logf(prod);
            out[b]         = X;
            out[BATCH + b] = X - logZ;
        }
    }
}

// ---------------------------------------------------------------------------
extern "C" void kernel_launch(void* const* d_in, const int* in_sizes, int n_in,
                              void* d_out, int out_size)
{
    const float* scores  = (const float*)d_in[0];  // (1024, 512, 48) f32
    const int*   target  = (const int*)  d_in[1];  // (1024, 512) i32
    const int*   lengths = (const int*)  d_in[2];  // (512,) i32
    const float* trans   = (const float*)d_in[3];  // (48, 48) f32
    float* out = (float*)d_out;                    // (2, 512) f32

    crf_rank_kernel<<<1, BATCH>>>(lengths);
    crf_mitm_kernel<<<BATCH / 4, 256>>>(scores, target, lengths, trans, out);
}